// round 13
// baseline (speedup 1.0000x reference)
#include <cuda_runtime.h>
#include <cuda_fp16.h>
#include <cstdint>
#include <cmath>

// ------------------------- scratch (device globals; no allocs allowed) ----
// Capacities: N*dpad <= 2^27, Q*dpad <= 2^23, N*mpad <= 2^25, Q*mpad <= 2^22
__device__ __half g_B1[(size_t)1 << 27];   // keys operand (x_mse * ||k||), fp16, stride dpad
__device__ float  g_B2[(size_t)1 << 25];   // signs * r_norm * scale * ||k||, fp32, stride mpad
__device__ __half g_A [(size_t)1 << 23];   // query fp16, stride dpad
__device__ float  g_Sq[(size_t)1 << 22];   // query @ S^T, fp32, stride mpad

#define MAXSEG 32   // supports d <= 1024

// ------------------------- PTX helpers -----------------------------------
__device__ __forceinline__ uint32_t smem_u32(const void* p) {
    uint32_t a;
    asm("{ .reg .u64 t; cvta.to.shared.u64 t, %1; cvt.u32.u64 %0, t; }" : "=r"(a) : "l"(p));
    return a;
}
__device__ __forceinline__ void cp_async16z(uint32_t s, const void* g, bool valid) {
    int sz = valid ? 16 : 0;
    asm volatile("cp.async.cg.shared.global [%0], [%1], 16, %2;" :: "r"(s), "l"(g), "r"(sz) : "memory");
}
__device__ __forceinline__ void cp_async_commit_wait() {
    asm volatile("cp.async.commit_group;" ::: "memory");
    asm volatile("cp.async.wait_group 0;" ::: "memory");
}
__device__ __forceinline__ void ldmatrix_x4(uint32_t& r0, uint32_t& r1, uint32_t& r2, uint32_t& r3, uint32_t addr) {
    asm volatile("ldmatrix.sync.aligned.m8n8.x4.shared.b16 {%0,%1,%2,%3}, [%4];"
                 : "=r"(r0), "=r"(r1), "=r"(r2), "=r"(r3) : "r"(addr));
}
__device__ __forceinline__ void mma16816(float* c, const uint32_t* a, const uint32_t* b) {
    asm volatile("mma.sync.aligned.m16n8k16.row.col.f32.f16.f16.f32 "
                 "{%0,%1,%2,%3}, {%4,%5,%6,%7}, {%8,%9}, {%0,%1,%2,%3};"
                 : "+f"(c[0]), "+f"(c[1]), "+f"(c[2]), "+f"(c[3])
                 : "r"(a[0]), "r"(a[1]), "r"(a[2]), "r"(a[3]), "r"(b[0]), "r"(b[1]));
}
__device__ __forceinline__ float warp_sum(float v) {
#pragma unroll
    for (int o = 16; o; o >>= 1) v += __shfl_xor_sync(0xffffffffu, v, o);
    return v;
}

// ------------------------- prep kernels (fully shape-general) -------------
// One warp per query row: write fp16 A (zero-padded to dpad), Sq = q @ S^T.
__global__ void prep_A_kernel(const float* __restrict__ query, const float* __restrict__ S,
                              int Q, int d, int dpad, int m, int mpad) {
    int wid = threadIdx.x >> 5, lane = threadIdx.x & 31;
    int q = blockIdx.x * 4 + wid;
    if (q >= Q) return;
    int nseg = (d + 31) >> 5;
    if (nseg > MAXSEG) nseg = MAXSEG;
    float xv[MAXSEG];
    for (int s = 0; s < nseg; s++) {
        int i = lane + s * 32;
        xv[s] = (i < d) ? query[(size_t)q * d + i] : 0.f;
    }
    for (int s = 0; s < nseg; s++) {
        int i = lane + s * 32;
        if (i < d) g_A[(size_t)q * dpad + i] = __float2half(xv[s]);
    }
    for (int i = d + lane; i < dpad; i += 32) g_A[(size_t)q * dpad + i] = __float2half(0.f);
    for (int j = 0; j < m; j++) {
        float p = 0.f;
        for (int s = 0; s < nseg; s++) {
            int i = lane + s * 32;
            if (i < d) p += xv[s] * __ldg(&S[(size_t)j * d + i]);
        }
        p = warp_sum(p);
        if (lane == 0) g_Sq[(size_t)q * mpad + j] = p;
    }
}

// One warp per key: norm, K-center MSE quant, residual norm, QJL signs.
__global__ void prep_keys_kernel(const float* __restrict__ keys, const float* __restrict__ cbk,
                                 const float* __restrict__ S,
                                 int N, int d, int dpad, int m, int mpad, int K, float scale) {
    int wid = threadIdx.x >> 5, lane = threadIdx.x & 31;
    int n = blockIdx.x * 8 + wid;
    if (n >= N) return;
    int nseg = (d + 31) >> 5;
    if (nseg > MAXSEG) nseg = MAXSEG;
    float xv[MAXSEG];
    float ssq = 0.f;
    for (int s = 0; s < nseg; s++) {
        int i = lane + s * 32;
        xv[s] = (i < d) ? keys[(size_t)n * d + i] : 0.f;
        ssq += xv[s] * xv[s];
    }
    float vn = sqrtf(warp_sum(ssq));
    float inv = 1.f / (vn + 1e-8f);
    float rsq = 0.f;
    for (int s = 0; s < nseg; s++) {
        int i = lane + s * 32;
        float x = xv[s] * inv;
        float c0 = __ldg(&cbk[0]);
        float best = c0, bd = fabsf(x - c0);
        for (int k = 1; k < K; k++) {
            float ck = __ldg(&cbk[k]);
            float dk = fabsf(x - ck);
            if (dk < bd) { bd = dk; best = ck; }
        }
        float r = (i < d) ? (x - best) : 0.f;
        if (i < d) g_B1[(size_t)n * dpad + i] = __float2half(best * vn);
        xv[s] = r;               // reuse register as residual
        rsq += r * r;
    }
    for (int i = d + lane; i < dpad; i += 32) g_B1[(size_t)n * dpad + i] = __float2half(0.f);
    float rn = sqrtf(warp_sum(rsq));
    float f = rn * scale * vn;
    for (int j = 0; j < m; j++) {
        float p = 0.f;
        for (int s = 0; s < nseg; s++) {
            int i = lane + s * 32;
            if (i < d) p += xv[s] * __ldg(&S[(size_t)j * d + i]);
        }
        p = warp_sum(p);
        if (lane == 0) g_B2[(size_t)n * mpad + j] = (p >= 0.f) ? f : -f;
    }
}

// ------------------------- main fused GEMM (mma.sync, shape-general) ------
// Per CTA: 128(M) x 128(N), K chunked by 64. 8 warps = 4(M) x 2(N); each warp
// 32x64 = 2x8 m16n8k16 tiles. SMEM chunk row stride 144 B (conflict-free
// ldmatrix). B2 and Sq tiles staged in SMEM with runtime stride mpad.
#define KC      64
#define PAD     144
#define SM_AS   0
#define SM_BS   (128 * PAD)                 // 18432
#define SM_B2   (2 * 128 * PAD)             // 36864

__global__ void __launch_bounds__(256, 2)
gemm_kernel(float* __restrict__ out, int Q, int N, int dpad, int m, int mpad, int mtiles) {
    extern __shared__ char smem[];
    uint32_t sb = smem_u32(smem);
    int tid = threadIdx.x, wid = tid >> 5, lane = tid & 31;
    int mb = blockIdx.x % mtiles;           // M fastest -> B tile L2 reuse
    int nb = blockIdx.x / mtiles;
    int q0 = mb * 128, n0 = nb * 128;
    uint32_t tile2 = 128u * (uint32_t)mpad * 4u;   // bytes of one B2/Sq tile

    // B2 tile [128][mpad] + Sq tile [128][mpad] (zfill OOB rows)
    int segs = mpad >> 2;                   // 16B chunks per row
    for (int idx = tid; idx < 128 * segs; idx += 256) {
        int row = idx / segs, sg = idx - row * segs;
        cp_async16z(sb + SM_B2 + (uint32_t)idx * 16,
                    g_B2 + (size_t)(n0 + row) * mpad + sg * 4, (n0 + row) < N);
        cp_async16z(sb + SM_B2 + tile2 + (uint32_t)idx * 16,
                    g_Sq + (size_t)(q0 + row) * mpad + sg * 4, (q0 + row) < Q);
    }

    int wm = wid & 3, wn = wid >> 2;
    float c[2][8][4];
#pragma unroll
    for (int mt = 0; mt < 2; mt++)
#pragma unroll
        for (int nt = 0; nt < 8; nt++)
#pragma unroll
            for (int k = 0; k < 4; k++) c[mt][nt][k] = 0.f;

    uint32_t a_row = (uint32_t)(wm * 32 + (lane & 15));
    uint32_t a_kof = (uint32_t)((lane >> 4) * 8);
    uint32_t b_row = (uint32_t)(wn * 64 + (lane & 7) + ((lane >> 4) << 3));
    uint32_t b_kof = (uint32_t)(((lane >> 3) & 1) * 8);

    int nchunks = dpad / KC;
    for (int ch = 0; ch < nchunks; ch++) {
#pragma unroll
        for (int i = 0; i < 4; i++) {
            int idx = tid + i * 256;        // 0..1023
            int row = idx >> 3, sg = idx & 7;
            uint32_t so = (uint32_t)(row * PAD + sg * 16);
            cp_async16z(sb + SM_AS + so,
                        g_A + (size_t)(q0 + row) * dpad + ch * KC + sg * 8, (q0 + row) < Q);
            cp_async16z(sb + SM_BS + so,
                        g_B1 + (size_t)(n0 + row) * dpad + ch * KC + sg * 8, (n0 + row) < N);
        }
        cp_async_commit_wait();
        __syncthreads();
#pragma unroll
        for (int s = 0; s < 4; s++) {
            int kb = s * 16;
            uint32_t a_frag[2][4];
#pragma unroll
            for (int mt = 0; mt < 2; mt++) {
                uint32_t addr = sb + SM_AS + (a_row + mt * 16) * PAD + (kb + a_kof) * 2;
                ldmatrix_x4(a_frag[mt][0], a_frag[mt][1], a_frag[mt][2], a_frag[mt][3], addr);
            }
            uint32_t b_frag[8][2];
#pragma unroll
            for (int p = 0; p < 4; p++) {
                uint32_t r0, r1, r2, r3;
                uint32_t addr = sb + SM_BS + (b_row + p * 16) * PAD + (kb + b_kof) * 2;
                ldmatrix_x4(r0, r1, r2, r3, addr);
                b_frag[2 * p][0] = r0;     b_frag[2 * p][1] = r1;
                b_frag[2 * p + 1][0] = r2; b_frag[2 * p + 1][1] = r3;
            }
#pragma unroll
            for (int mt = 0; mt < 2; mt++)
#pragma unroll
                for (int nt = 0; nt < 8; nt++)
                    mma16816(c[mt][nt], a_frag[mt], b_frag[nt]);
        }
        __syncthreads();
    }

    // ---- epilogue: rank-m correction from SMEM + guarded store ----
    int g = lane >> 2;                      // row within 8-row group
    int cc = (lane & 3) * 2;                // col pair
    const float* b2s = (const float*)(smem + SM_B2);
    const float* sqs = b2s + (size_t)128 * mpad;
    bool evenN = (N & 1) == 0;
#pragma unroll
    for (int mt = 0; mt < 2; mt++) {
        int rl0 = wm * 32 + mt * 16 + g;    // local q row in tile
        int qr0 = q0 + rl0, qr1 = qr0 + 8;
        float* o0 = out + (size_t)qr0 * N + n0;
        float* o1 = out + (size_t)qr1 * N + n0;
#pragma unroll
        for (int nt = 0; nt < 8; nt++) {
            int nl = wn * 64 + nt * 8 + cc;
            float e00 = 0.f, e01 = 0.f, e10 = 0.f, e11 = 0.f;
            for (int j = 0; j < m; j++) {
                float a0 = sqs[(size_t)rl0 * mpad + j];
                float a1 = sqs[(size_t)(rl0 + 8) * mpad + j];
                float t0 = b2s[(size_t)nl * mpad + j];
                float t1 = b2s[(size_t)(nl + 1) * mpad + j];
                e00 += a0 * t0;  e01 += a0 * t1;
                e10 += a1 * t0;  e11 += a1 * t1;
            }
            int gn = n0 + nl;
            float v00 = c[mt][nt][0] + e00, v01 = c[mt][nt][1] + e01;
            float v10 = c[mt][nt][2] + e10, v11 = c[mt][nt][3] + e11;
            if (qr0 < Q) {
                if (evenN && gn + 1 < N)      *(float2*)(o0 + nl) = make_float2(v00, v01);
                else { if (gn < N) o0[nl] = v00; if (gn + 1 < N) o0[nl + 1] = v01; }
            }
            if (qr1 < Q) {
                if (evenN && gn + 1 < N)      *(float2*)(o1 + nl) = make_float2(v10, v11);
                else { if (gn < N) o1[nl] = v10; if (gn + 1 < N) o1[nl + 1] = v11; }
            }
        }
    }
}

// ------------------------- launcher --------------------------------------
// Bind buffers by size rank (keys > query > S > codebook) and derive shapes
// from ELEMENT counts:  d = sqrt(|query|*|keys| / out_size),
// Q = |query|/d, N = |keys|/d, m = |S|/d, K = |codebook|.
extern "C" void kernel_launch(void* const* d_in, const int* in_sizes, int n_in,
                              void* d_out, int out_size) {
    int idx[16];
    int nn = n_in < 16 ? n_in : 16;
    for (int i = 0; i < nn; i++) idx[i] = i;
    for (int i = 1; i < nn; i++) {
        int v = idx[i], j = i - 1;
        while (j >= 0 && (long long)in_sizes[idx[j]] < (long long)in_sizes[v]) {
            idx[j + 1] = idx[j]; j--;
        }
        idx[j + 1] = v;
    }
    const float* keys     = (const float*)d_in[idx[0]];
    const float* query    = (const float*)d_in[idx[1]];
    const float* S        = (const float*)d_in[idx[2]];
    const float* codebook = (const float*)d_in[idx[3]];
    long long sk = in_sizes[idx[0]], sq = in_sizes[idx[1]];
    long long ss = in_sizes[idx[2]], sc = in_sizes[idx[3]];

    int d = (int)llround(sqrt((double)sq * (double)sk / (double)out_size));
    if (d < 1) d = 1;
    int Q = (int)(sq / d);
    int N = (int)(sk / d);
    int m = (int)(ss / d); if (m < 1) m = 1;
    int K = (int)sc;       if (K < 1) K = 1;
    int dpad = (d + 63) & ~63;
    int mpad = (m + 3) & ~3;
    float scale = 1.2533141373155003f / (float)m;   // sqrt(pi/2)/m
    int mtiles = (Q + 127) / 128;
    int ntiles = (N + 127) / 128;
    float* out = (float*)d_out;

    int gemm_smem = SM_B2 + 2 * 128 * mpad * 4;
    cudaFuncSetAttribute(gemm_kernel, cudaFuncAttributeMaxDynamicSharedMemorySize, gemm_smem);

    prep_A_kernel<<<(Q + 3) / 4, 128>>>(query, S, Q, d, dpad, m, mpad);
    prep_keys_kernel<<<(N + 7) / 8, 256>>>(keys, codebook, S, N, d, dpad, m, mpad, K, scale);
    gemm_kernel<<<mtiles * ntiles, 256, gemm_smem>>>(out, Q, N, dpad, m, mpad, mtiles);
}

// round 17
// speedup vs baseline: 24.7517x; 24.7517x over previous
#include <cuda_runtime.h>
#include <cuda_fp16.h>
#include <cstdint>
#include <cmath>

// ------------------------- scratch (device globals; no allocs allowed) ----
// Caps: N*Ke <= 2^27, Q*Ke <= 2^23, N*dpad <= 2^25, m*dpad <= 2^20, N <= 2^18
__device__ __half g_B1[(size_t)1 << 27];   // [N][Ke]: x_mse*||k|| | sign*f   (fp16)
__device__ __half g_A [(size_t)1 << 23];   // [Q][Ke]: query | Sq            (fp16)
__device__ __half g_R1[(size_t)1 << 25];   // [N][dpad]: residual hi         (fp16)
__device__ __half g_R2[(size_t)1 << 25];   // [N][dpad]: residual lo         (fp16)
__device__ __half g_S1[(size_t)1 << 20];   // [m][dpad]: S hi
__device__ __half g_S2[(size_t)1 << 20];   // [m][dpad]: S lo
__device__ float  g_F [(size_t)1 << 18];   // [N]: r_norm * scale * ||k||

// ------------------------- PTX helpers -----------------------------------
__device__ __forceinline__ uint32_t smem_u32(const void* p) {
    uint32_t a;
    asm("{ .reg .u64 t; cvta.to.shared.u64 t, %1; cvt.u32.u64 %0, t; }" : "=r"(a) : "l"(p));
    return a;
}
__device__ __forceinline__ void cp_async16z(uint32_t s, const void* g, bool valid) {
    int sz = valid ? 16 : 0;
    asm volatile("cp.async.cg.shared.global [%0], [%1], 16, %2;" :: "r"(s), "l"(g), "r"(sz) : "memory");
}
__device__ __forceinline__ void cp_commit() {
    asm volatile("cp.async.commit_group;" ::: "memory");
}
__device__ __forceinline__ void cp_wait0() {
    asm volatile("cp.async.wait_group 0;" ::: "memory");
}
__device__ __forceinline__ void cp_wait1() {
    asm volatile("cp.async.wait_group 1;" ::: "memory");
}
__device__ __forceinline__ void ldmatrix_x4(uint32_t& r0, uint32_t& r1, uint32_t& r2, uint32_t& r3, uint32_t addr) {
    asm volatile("ldmatrix.sync.aligned.m8n8.x4.shared.b16 {%0,%1,%2,%3}, [%4];"
                 : "=r"(r0), "=r"(r1), "=r"(r2), "=r"(r3) : "r"(addr));
}
__device__ __forceinline__ void mma16816(float* c, const uint32_t* a, const uint32_t* b) {
    asm volatile("mma.sync.aligned.m16n8k16.row.col.f32.f16.f16.f32 "
                 "{%0,%1,%2,%3}, {%4,%5,%6,%7}, {%8,%9}, {%0,%1,%2,%3};"
                 : "+f"(c[0]), "+f"(c[1]), "+f"(c[2]), "+f"(c[3])
                 : "r"(a[0]), "r"(a[1]), "r"(a[2]), "r"(a[3]), "r"(b[0]), "r"(b[1]));
}
__device__ __forceinline__ float warp_sum(float v) {
#pragma unroll
    for (int o = 16; o; o >>= 1) v += __shfl_xor_sync(0xffffffffu, v, o);
    return v;
}

// ------------------------- tiny kernels -----------------------------------
// S -> fp16 hi/lo split, padded [m][dpad]
__global__ void s16_kernel(const float* __restrict__ S, int m, int d, int dpad) {
    int idx = blockIdx.x * 256 + threadIdx.x;
    if (idx >= m * dpad) return;
    int j = idx / dpad, i = idx - j * dpad;
    float v = (i < d) ? S[(size_t)j * d + i] : 0.f;
    __half h = __float2half(v);
    g_S1[idx] = h;
    g_S2[idx] = __float2half(v - __half2float(h));
}

// One block per query row: A_ext = [query fp16 | Sq fp16], zero-padded.
__global__ void prep_A_kernel(const float* __restrict__ query, const float* __restrict__ S,
                              int Q, int d, int dpad, int m, int mext, int Ke) {
    extern __shared__ float sq[];
    int q = blockIdx.x, tid = threadIdx.x;
    int wid = tid >> 5, lane = tid & 31;
    for (int i = tid; i < d; i += 256) sq[i] = query[(size_t)q * d + i];
    __syncthreads();
    for (int i = tid; i < dpad; i += 256)
        g_A[(size_t)q * Ke + i] = __float2half(i < d ? sq[i] : 0.f);
    for (int j = wid; j < m; j += 8) {
        float p = 0.f;
        const float* srow = S + (size_t)j * d;
        for (int i = lane; i < d; i += 32) p += sq[i] * srow[i];
        p = warp_sum(p);
        if (lane == 0) g_A[(size_t)q * Ke + dpad + j] = __float2half(p);
    }
    for (int j = m + tid; j < mext; j += 256)
        g_A[(size_t)q * Ke + dpad + j] = __float2half(0.f);
}

// One warp per key: norm, binary-search MSE quant (sorted codebook),
// residual hi/lo -> g_R1/g_R2, B1 core = x_mse*||k||, f -> g_F.
#define MAXSEG 32
__global__ void prep_keys_kernel(const float* __restrict__ keys, const float* __restrict__ cbk,
                                 int N, int d, int dpad, int K, int Ke, float scale) {
    extern __shared__ float scb[];
    for (int i = threadIdx.x; i < K; i += blockDim.x) scb[i] = cbk[i];
    __syncthreads();
    int wid = threadIdx.x >> 5, lane = threadIdx.x & 31;
    int n = blockIdx.x * 8 + wid;
    if (n >= N) return;
    int nseg = (d + 31) >> 5;
    if (nseg > MAXSEG) nseg = MAXSEG;
    float xv[MAXSEG];
    float ssq = 0.f;
    for (int s = 0; s < nseg; s++) {
        int i = lane + s * 32;
        xv[s] = (i < d) ? keys[(size_t)n * d + i] : 0.f;
        ssq += xv[s] * xv[s];
    }
    float vn = sqrtf(warp_sum(ssq));
    float inv = 1.f / (vn + 1e-8f);
    float rsq = 0.f;
    for (int s = 0; s < nseg; s++) {
        int i = lane + s * 32;
        float x = xv[s] * inv;
        int lo = 0, hi = K;
        while (lo < hi) { int mid = (lo + hi) >> 1; if (scb[mid] < x) lo = mid + 1; else hi = mid; }
        float best;
        if (lo == 0) best = scb[0];
        else if (lo == K) best = scb[K - 1];
        else {
            float cp = scb[lo - 1], cs = scb[lo];
            best = (x - cp <= cs - x) ? cp : cs;   // tie -> lower index (argmin-first)
        }
        float r = (i < d) ? (x - best) : 0.f;
        if (i < d) g_B1[(size_t)n * Ke + i] = __float2half(best * vn);
        __half r1 = __float2half(r);
        g_R1[(size_t)n * dpad + i] = r1;
        g_R2[(size_t)n * dpad + i] = __float2half(r - __half2float(r1));
        rsq += r * r;
    }
    for (int i = d + lane; i < dpad; i += 32) {
        g_B1[(size_t)n * Ke + i] = __float2half(0.f);
        g_R1[(size_t)n * dpad + i] = __float2half(0.f);
        g_R2[(size_t)n * dpad + i] = __float2half(0.f);
    }
    float rn = sqrtf(warp_sum(rsq));
    if (lane == 0) g_F[n] = rn * scale * vn;
}

// ------------------------- sign GEMM: P = R @ S^T (split fp16 x3) ---------
// P = R1*S1 + R2*S1 + R1*S2  (drops O(eps^2) R2*S2) -> exact-enough signs.
// CTA = 128 keys. Loop jc over mext in steps of 64, K chunked by 64.
#define KC    64
#define PAD   144
#define SG_R1 0
#define SG_R2 (128 * PAD)
#define SG_S1 (2 * 128 * PAD)
#define SG_S2 (2 * 128 * PAD + 64 * PAD)
#define SG_TOT (2 * 128 * PAD + 2 * 64 * PAD)   // 55296

__global__ void __launch_bounds__(256, 2)
sign_gemm_kernel(int N, int dpad, int m, int mext, int Ke) {
    extern __shared__ char smem[];
    uint32_t sb = smem_u32(smem);
    int tid = threadIdx.x, wid = tid >> 5, lane = tid & 31;
    int n0 = blockIdx.x * 128;
    int wm = wid & 3, wn = wid >> 2;

    uint32_t a_row = (uint32_t)(wm * 32 + (lane & 15));
    uint32_t a_kof = (uint32_t)((lane >> 4) * 8);
    uint32_t b_row = (uint32_t)(wn * 32 + (lane & 7) + ((lane >> 4) << 3));
    uint32_t b_kof = (uint32_t)(((lane >> 3) & 1) * 8);
    int g = lane >> 2, cc = (lane & 3) * 2;
    int nchunks = dpad / KC;

    for (int jc = 0; jc < mext; jc += 64) {
        float c[2][4][4];
#pragma unroll
        for (int mt = 0; mt < 2; mt++)
#pragma unroll
            for (int nt = 0; nt < 4; nt++)
#pragma unroll
                for (int k = 0; k < 4; k++) c[mt][nt][k] = 0.f;

        for (int ch = 0; ch < nchunks; ch++) {
#pragma unroll
            for (int i = 0; i < 4; i++) {          // R1,R2: 128 rows x 8 segs
                int idx = tid + i * 256;
                int row = idx >> 3, sg = idx & 7;
                uint32_t so = (uint32_t)(row * PAD + sg * 16);
                size_t go = (size_t)(n0 + row) * dpad + ch * KC + sg * 8;
                bool v = (n0 + row) < N;
                cp_async16z(sb + SG_R1 + so, g_R1 + go, v);
                cp_async16z(sb + SG_R2 + so, g_R2 + go, v);
            }
#pragma unroll
            for (int i = 0; i < 2; i++) {          // S1,S2: 64 rows x 8 segs
                int idx = tid + i * 256;
                int row = idx >> 3, sg = idx & 7;
                uint32_t so = (uint32_t)(row * PAD + sg * 16);
                size_t go = (size_t)(jc + row) * dpad + ch * KC + sg * 8;
                bool v = (jc + row) < m;
                cp_async16z(sb + SG_S1 + so, g_S1 + go, v);
                cp_async16z(sb + SG_S2 + so, g_S2 + go, v);
            }
            cp_commit();
            cp_wait0();
            __syncthreads();
#pragma unroll
            for (int s = 0; s < 4; s++) {
                int kb = s * 16;
                uint32_t a1[2][4], a2[2][4];
#pragma unroll
                for (int mt = 0; mt < 2; mt++) {
                    uint32_t ro = (a_row + mt * 16) * PAD + (kb + a_kof) * 2;
                    ldmatrix_x4(a1[mt][0], a1[mt][1], a1[mt][2], a1[mt][3], sb + SG_R1 + ro);
                    ldmatrix_x4(a2[mt][0], a2[mt][1], a2[mt][2], a2[mt][3], sb + SG_R2 + ro);
                }
                uint32_t b1[4][2], b2[4][2];
#pragma unroll
                for (int p = 0; p < 2; p++) {
                    uint32_t ro = (b_row + p * 16) * PAD + (kb + b_kof) * 2;
                    uint32_t r0, r1, r2, r3;
                    ldmatrix_x4(r0, r1, r2, r3, sb + SG_S1 + ro);
                    b1[2 * p][0] = r0;     b1[2 * p][1] = r1;
                    b1[2 * p + 1][0] = r2; b1[2 * p + 1][1] = r3;
                    ldmatrix_x4(r0, r1, r2, r3, sb + SG_S2 + ro);
                    b2[2 * p][0] = r0;     b2[2 * p][1] = r1;
                    b2[2 * p + 1][0] = r2; b2[2 * p + 1][1] = r3;
                }
#pragma unroll
                for (int mt = 0; mt < 2; mt++)
#pragma unroll
                    for (int nt = 0; nt < 4; nt++) {
                        mma16816(c[mt][nt], a1[mt], b1[nt]);
                        mma16816(c[mt][nt], a2[mt], b1[nt]);
                        mma16816(c[mt][nt], a1[mt], b2[nt]);
                    }
            }
            __syncthreads();
        }

        // write signs: B1[n][dpad + jc + j] = copysign(f, P)  (0 for j >= m)
#pragma unroll
        for (int mt = 0; mt < 2; mt++) {
            int r0 = wm * 32 + mt * 16 + g;
            int n_0 = n0 + r0, n_1 = n_0 + 8;
            float f0 = (n_0 < N) ? g_F[n_0] : 0.f;
            float f1 = (n_1 < N) ? g_F[n_1] : 0.f;
#pragma unroll
            for (int nt = 0; nt < 4; nt++) {
                int jl = wn * 32 + nt * 8 + cc;
                int j0 = jc + jl, j1 = j0 + 1;
                if (n_0 < N) {
                    g_B1[(size_t)n_0 * Ke + dpad + j0] =
                        __float2half(j0 < m ? copysignf(f0, c[mt][nt][0]) : 0.f);
                    g_B1[(size_t)n_0 * Ke + dpad + j1] =
                        __float2half(j1 < m ? copysignf(f0, c[mt][nt][1]) : 0.f);
                }
                if (n_1 < N) {
                    g_B1[(size_t)n_1 * Ke + dpad + j0] =
                        __float2half(j0 < m ? copysignf(f1, c[mt][nt][2]) : 0.f);
                    g_B1[(size_t)n_1 * Ke + dpad + j1] =
                        __float2half(j1 < m ? copysignf(f1, c[mt][nt][3]) : 0.f);
                }
            }
        }
        if (jc + 64 < mext) __syncthreads();
    }
}

// ------------------------- main GEMM: out = A_ext @ B1_ext^T --------------
// 2-stage cp.async pipeline; per CTA 128x128, 8 warps = 4(M) x 2(N).
#define ST_SZ (2 * 128 * PAD)             // one stage: A tile + B tile = 36864
#define SM_TOT (2 * ST_SZ)                // 73728

__global__ void __launch_bounds__(256, 2)
gemm_kernel(float* __restrict__ out, int Q, int N, int Ke, int mtiles) {
    extern __shared__ char smem[];
    uint32_t sb = smem_u32(smem);
    int tid = threadIdx.x, wid = tid >> 5, lane = tid & 31;
    int mb = blockIdx.x % mtiles;          // M fastest -> B tile L2 reuse
    int nb = blockIdx.x / mtiles;
    int q0 = mb * 128, n0 = nb * 128;
    int wm = wid & 3, wn = wid >> 2;

    float c[2][8][4];
#pragma unroll
    for (int mt = 0; mt < 2; mt++)
#pragma unroll
        for (int nt = 0; nt < 8; nt++)
#pragma unroll
            for (int k = 0; k < 4; k++) c[mt][nt][k] = 0.f;

    uint32_t a_row = (uint32_t)(wm * 32 + (lane & 15));
    uint32_t a_kof = (uint32_t)((lane >> 4) * 8);
    uint32_t b_row = (uint32_t)(wn * 64 + (lane & 7) + ((lane >> 4) << 3));
    uint32_t b_kof = (uint32_t)(((lane >> 3) & 1) * 8);

    int nchunks = Ke / KC;
    int lrow = tid >> 3, lsg = tid & 7;    // 32 rows per pass, 8 segs

    // chunk loader: stage st, k-chunk ch
    auto load_chunk = [&](int ch, int st) {
        uint32_t base = sb + (uint32_t)st * ST_SZ;
#pragma unroll
        for (int i = 0; i < 4; i++) {
            int row = lrow + i * 32;
            uint32_t so = (uint32_t)(row * PAD + lsg * 16);
            cp_async16z(base + so,
                        g_A + (size_t)(q0 + row) * Ke + ch * KC + lsg * 8, (q0 + row) < Q);
            cp_async16z(base + 128 * PAD + so,
                        g_B1 + (size_t)(n0 + row) * Ke + ch * KC + lsg * 8, (n0 + row) < N);
        }
        cp_commit();
    };

    load_chunk(0, 0);
    for (int ch = 0; ch < nchunks; ch++) {
        if (ch + 1 < nchunks) { load_chunk(ch + 1, (ch + 1) & 1); cp_wait1(); }
        else cp_wait0();
        __syncthreads();
        uint32_t base = sb + (uint32_t)(ch & 1) * ST_SZ;
#pragma unroll
        for (int s = 0; s < 4; s++) {
            int kb = s * 16;
            uint32_t a_frag[2][4];
#pragma unroll
            for (int mt = 0; mt < 2; mt++) {
                uint32_t addr = base + (a_row + mt * 16) * PAD + (kb + a_kof) * 2;
                ldmatrix_x4(a_frag[mt][0], a_frag[mt][1], a_frag[mt][2], a_frag[mt][3], addr);
            }
            uint32_t b_frag[8][2];
#pragma unroll
            for (int p = 0; p < 4; p++) {
                uint32_t r0, r1, r2, r3;
                uint32_t addr = base + 128 * PAD + (b_row + p * 16) * PAD + (kb + b_kof) * 2;
                ldmatrix_x4(r0, r1, r2, r3, addr);
                b_frag[2 * p][0] = r0;     b_frag[2 * p][1] = r1;
                b_frag[2 * p + 1][0] = r2; b_frag[2 * p + 1][1] = r3;
            }
#pragma unroll
            for (int mt = 0; mt < 2; mt++)
#pragma unroll
                for (int nt = 0; nt < 8; nt++)
                    mma16816(c[mt][nt], a_frag[mt], b_frag[nt]);
        }
        __syncthreads();                   // stage reusable (ch+2's load) only after all consumed
    }

    // ---- epilogue: pure store ----
    int g = lane >> 2, cc = (lane & 3) * 2;
    bool evenN = (N & 1) == 0;
#pragma unroll
    for (int mt = 0; mt < 2; mt++) {
        int qr0 = q0 + wm * 32 + mt * 16 + g, qr1 = qr0 + 8;
        float* o0 = out + (size_t)qr0 * N + n0;
        float* o1 = out + (size_t)qr1 * N + n0;
#pragma unroll
        for (int nt = 0; nt < 8; nt++) {
            int nl = wn * 64 + nt * 8 + cc;
            int gn = n0 + nl;
            if (qr0 < Q) {
                if (evenN && gn + 1 < N) *(float2*)(o0 + nl) = make_float2(c[mt][nt][0], c[mt][nt][1]);
                else { if (gn < N) o0[nl] = c[mt][nt][0]; if (gn + 1 < N) o0[nl + 1] = c[mt][nt][1]; }
            }
            if (qr1 < Q) {
                if (evenN && gn + 1 < N) *(float2*)(o1 + nl) = make_float2(c[mt][nt][2], c[mt][nt][3]);
                else { if (gn < N) o1[nl] = c[mt][nt][2]; if (gn + 1 < N) o1[nl + 1] = c[mt][nt][3]; }
            }
        }
    }
}

// ------------------------- launcher --------------------------------------
// Bind by size rank (keys > query > S > codebook); derive shapes from
// ELEMENT counts: d = sqrt(|query|*|keys|/out_size), Q=|query|/d, N=|keys|/d,
// m=|S|/d, K=|codebook|.
extern "C" void kernel_launch(void* const* d_in, const int* in_sizes, int n_in,
                              void* d_out, int out_size) {
    int idx[16];
    int nn = n_in < 16 ? n_in : 16;
    for (int i = 0; i < nn; i++) idx[i] = i;
    for (int i = 1; i < nn; i++) {
        int v = idx[i], j = i - 1;
        while (j >= 0 && (long long)in_sizes[idx[j]] < (long long)in_sizes[v]) {
            idx[j + 1] = idx[j]; j--;
        }
        idx[j + 1] = v;
    }
    const float* keys     = (const float*)d_in[idx[0]];
    const float* query    = (const float*)d_in[idx[1]];
    const float* S        = (const float*)d_in[idx[2]];
    const float* codebook = (const float*)d_in[idx[3]];
    long long sk = in_sizes[idx[0]], sq = in_sizes[idx[1]];
    long long ss = in_sizes[idx[2]], sc = in_sizes[idx[3]];

    int d = (int)llround(sqrt((double)sq * (double)sk / (double)out_size));
    if (d < 1) d = 1;
    int Q = (int)(sq / d);
    int N = (int)(sk / d);
    int m = (int)(ss / d); if (m < 1) m = 1;
    int K = (int)sc;       if (K < 1) K = 1;
    int dpad = (d + 63) & ~63;
    int mext = (m + 63) & ~63;
    int Ke = dpad + mext;
    float scale = 1.2533141373155003f / (float)m;   // sqrt(pi/2)/m
    int mtiles = (Q + 127) / 128;
    int ntiles = (N + 127) / 128;
    float* out = (float*)d_out;

    cudaFuncSetAttribute(sign_gemm_kernel, cudaFuncAttributeMaxDynamicSharedMemorySize, SG_TOT);
    cudaFuncSetAttribute(gemm_kernel, cudaFuncAttributeMaxDynamicSharedMemorySize, SM_TOT);

    s16_kernel<<<(m * dpad + 255) / 256, 256>>>(S, m, d, dpad);
    prep_A_kernel<<<Q, 256, (size_t)d * sizeof(float)>>>(query, S, Q, d, dpad, m, mext, Ke);
    prep_keys_kernel<<<(N + 7) / 8, 256, (size_t)K * sizeof(float)>>>(keys, codebook, N, d, dpad, K, Ke, scale);
    sign_gemm_kernel<<<ntiles, 256, SG_TOT>>>(N, dpad, m, mext, Ke);
    gemm_kernel<<<mtiles * ntiles, 256, SM_TOT>>>(out, Q, N, Ke, mtiles);
}